// round 14
// baseline (speedup 1.0000x reference)
#include <cuda_runtime.h>
#include <cstdint>
#include <math.h>

// ===========================================================================
// LSTM cell, legacy tensor path (sm_100: no tcgen05).
//   Prepass A: tf32-round concat(h_t,x), store k-PERMUTED per 32-block:
//     pos(k) = (k&3)*8 + ((k>>2)&7)  -> mma fragment elems become contiguous.
//   Prepass W: tiled transpose to [gate][h][k-permuted] (n-major), tf32-round.
//   GEMM: TF32 mma.sync m16n8k8, 3-stage cp.async pipeline; fragment loads
//   are LDS.128 (2 per row) instead of scalar LDS (4x fewer issue slots).
//   CTA tile: 128 rows x (4 gates x 32 H-cols); fused LSTM epilogue.
// ===========================================================================

namespace {
constexpr int Bsz = 8192, Hsz = 1024, Ksz = 2048;
constexpr int BM = 128, BK = 32;
constexpr int LDA = 36;              // 32 floats + 4 pad (conflict-free LDS.128)
constexpr int LDB = 36;
constexpr int A_STRIDE = BM * LDA;   // 4608 floats (128 rows)
constexpr int B_STRIDE = 128 * LDB;  // 4608 floats (128 n-rows)
constexpr int NSTAGE = 3;
constexpr int SMEM_FLOATS = NSTAGE * (A_STRIDE + B_STRIDE);   // 27648
constexpr int SMEM_BYTES = SMEM_FLOATS * 4;                   // 110592

constexpr size_t A_ELEMS = (size_t)Bsz * Ksz;   // 16M
constexpr size_t W_ELEMS = 4ull * Ksz * Hsz;    // 8M (Ksz*Hsz = 2^21)
}

__device__ float g_A[A_ELEMS];   // [m][k-permuted], tf32-rounded
__device__ float g_W[W_ELEMS];   // [gate][h][k-permuted], tf32-rounded (transposed)

__device__ __forceinline__ void cp16(float* smem_dst, const float* gsrc) {
    uint32_t s = (uint32_t)__cvta_generic_to_shared(smem_dst);
    asm volatile("cp.async.cg.shared.global [%0], [%1], 16;" :: "r"(s), "l"(gsrc));
}
__device__ __forceinline__ uint32_t f2tf(float f) {
    uint32_t r; asm("cvt.rna.tf32.f32 %0, %1;" : "=r"(r) : "f"(f)); return r;
}
__device__ __forceinline__ float tf32r(float f) { return __uint_as_float(f2tf(f)); }
__device__ __forceinline__ void mma_tf32(float* c, uint32_t a0, uint32_t a1,
                                         uint32_t a2, uint32_t a3,
                                         uint32_t b0, uint32_t b1) {
    asm volatile(
        "mma.sync.aligned.m16n8k8.row.col.f32.tf32.tf32.f32 "
        "{%0,%1,%2,%3}, {%4,%5,%6,%7}, {%8,%9}, {%0,%1,%2,%3};"
        : "+f"(c[0]), "+f"(c[1]), "+f"(c[2]), "+f"(c[3])
        : "r"(a0), "r"(a1), "r"(a2), "r"(a3), "r"(b0), "r"(b1));
}
__device__ __forceinline__ float sigf(float v) { return 1.f / (1.f + __expf(-v)); }
__device__ __forceinline__ int kperm(int k) { return ((k & 3) << 3) | ((k >> 2) & 7); }

// ---------------------------------------------------------------------------
// Prepass A: round + pack concat(h|x) with per-32-block k permutation.
__global__ __launch_bounds__(256)
void lstm_prepass_a(const float* __restrict__ h_t, const float* __restrict__ x)
{
    const size_t i4 = (size_t)blockIdx.x * 256 + threadIdx.x;
    if (i4 >= A_ELEMS / 4) return;
    const size_t e = i4 * 4;
    const int m = (int)(e >> 11), k = (int)(e & 2047);
    const float* src = (k < 1024) ? (h_t + (size_t)m * 1024 + k)
                                  : (x + (size_t)m * 1024 + (k - 1024));
    const float4 v = *reinterpret_cast<const float4*>(src);
    float* dstb = g_A + (size_t)m * Ksz + (k & ~31);
    dstb[kperm(k + 0)] = tf32r(v.x);
    dstb[kperm(k + 1)] = tf32r(v.y);
    dstb[kperm(k + 2)] = tf32r(v.z);
    dstb[kperm(k + 3)] = tf32r(v.w);
}

// Prepass W: tiled transpose [k][h] -> [gate][h][k-permuted], tf32-rounded.
__global__ __launch_bounds__(256)
void lstm_prepass_w(const float* __restrict__ Wf, const float* __restrict__ Wi,
                    const float* __restrict__ Wc, const float* __restrict__ Wo)
{
    __shared__ float t[32][33];
    const int gate = blockIdx.z;
    const float* W = (gate == 0) ? Wf : (gate == 1) ? Wi : (gate == 2) ? Wc : Wo;
    const int k0 = blockIdx.x * 32, h0 = blockIdx.y * 32;
    const int tx = threadIdx.x, ty = threadIdx.y;   // 32 x 8
    #pragma unroll
    for (int i = 0; i < 4; ++i)
        t[ty + i * 8][tx] = tf32r(W[(size_t)(k0 + ty + i * 8) * Hsz + h0 + tx]);
    __syncthreads();
    float* dst = g_W + (size_t)gate * (Ksz * Hsz);
    const int kp = k0 + kperm(tx);
    #pragma unroll
    for (int i = 0; i < 4; ++i)
        dst[(size_t)(h0 + ty + i * 8) * Ksz + kp] = t[tx][ty + i * 8];
}

// ---------------------------------------------------------------------------
__device__ __forceinline__ void prefetch_tiles(float* smem, int stage, int k0,
                                               int m0, int h0, int tid)
{
    float* As  = smem + stage * A_STRIDE;
    float* Bsm = smem + NSTAGE * A_STRIDE + stage * B_STRIDE;
    #pragma unroll
    for (int it = 0; it < 4; ++it) {            // A: 128 m-rows x 32 floats
        const int lin = tid + it * 256;
        const int r = lin >> 3, q = lin & 7;
        cp16(&As[r * LDA + q * 4], g_A + (size_t)(m0 + r) * Ksz + k0 + q * 4);
    }
    #pragma unroll
    for (int it = 0; it < 4; ++it) {            // B: 128 n-rows (4 gates x 32 h)
        const int lin = tid + it * 256;
        const int r = lin >> 3, q = lin & 7;    // r = gate*32 + hc
        const int gate = r >> 5, hc = r & 31;
        cp16(&Bsm[r * LDB + q * 4],
             g_W + (size_t)gate * (Ksz * Hsz) + (size_t)(h0 + hc) * Ksz + k0 + q * 4);
    }
    asm volatile("cp.async.commit_group;");
}

__global__ __launch_bounds__(256, 2)
void lstm_gemm_fused(const float* __restrict__ c_t,
                     const float* __restrict__ bfp, const float* __restrict__ bip,
                     const float* __restrict__ bcp, const float* __restrict__ bop,
                     float* __restrict__ out, int nchunks)
{
    extern __shared__ float smem[];
    const int tid = threadIdx.x;
    const int m0 = blockIdx.y * BM;
    const int h0 = blockIdx.x * 32;            // 32 H-cols per CTA, all 4 gates

    const int warp = tid >> 5, lane = tid & 31;
    const int wm = warp >> 2, wn = warp & 3;   // 2 x 4 warps
    const int rb = wm * 64;
    const int g = lane >> 2, tg = lane & 3;

    float acc[4][4][4];                        // [m-frag][gate][reg]
    #pragma unroll
    for (int i = 0; i < 4; ++i)
        #pragma unroll
        for (int j = 0; j < 4; ++j)
            #pragma unroll
            for (int t = 0; t < 4; ++t) acc[i][j][t] = 0.f;

    const int KT = Ksz / BK;   // 64
    prefetch_tiles(smem, 0, 0, m0, h0, tid);
    prefetch_tiles(smem, 1, BK, m0, h0, tid);

    int stage = 0;
    for (int kt = 0; kt < KT; ++kt) {
        if (kt + 1 < KT) asm volatile("cp.async.wait_group 1;");
        else             asm volatile("cp.async.wait_group 0;");
        __syncthreads();
        if (kt + 2 < KT)
            prefetch_tiles(smem, (stage + 2) % NSTAGE, (kt + 2) * BK, m0, h0, tid);

        const float* As  = smem + stage * A_STRIDE;
        const float* Bsm = smem + NSTAGE * A_STRIDE + stage * B_STRIDE;

        // permuted row: 8 floats at tg*8 cover cols {kk+tg, kk+tg+4 : kk in 0,8,16,24}
        // half h2: float4 at tg*8 + h2*4 -> (x,y)=kk(h2*16), (z,w)=kk(h2*16+8)
        #pragma unroll
        for (int h2 = 0; h2 < 2; ++h2) {
            float4 av[8];
            #pragma unroll
            for (int i = 0; i < 4; ++i) {
                const int r0 = rb + i * 16 + g;
                av[2*i]   = *reinterpret_cast<const float4*>(&As[r0 * LDA + tg * 8 + h2 * 4]);
                av[2*i+1] = *reinterpret_cast<const float4*>(&As[(r0 + 8) * LDA + tg * 8 + h2 * 4]);
            }
            float4 bv[4];
            #pragma unroll
            for (int gate = 0; gate < 4; ++gate) {
                const int c0 = gate * 32 + wn * 8 + g;
                bv[gate] = *reinterpret_cast<const float4*>(&Bsm[c0 * LDB + tg * 8 + h2 * 4]);
            }
            #pragma unroll
            for (int i = 0; i < 4; ++i)
                #pragma unroll
                for (int gate = 0; gate < 4; ++gate)
                    mma_tf32(acc[i][gate],
                             __float_as_uint(av[2*i].x), __float_as_uint(av[2*i+1].x),
                             __float_as_uint(av[2*i].y), __float_as_uint(av[2*i+1].y),
                             __float_as_uint(bv[gate].x), __float_as_uint(bv[gate].y));
            #pragma unroll
            for (int i = 0; i < 4; ++i)
                #pragma unroll
                for (int gate = 0; gate < 4; ++gate)
                    mma_tf32(acc[i][gate],
                             __float_as_uint(av[2*i].z), __float_as_uint(av[2*i+1].z),
                             __float_as_uint(av[2*i].w), __float_as_uint(av[2*i+1].w),
                             __float_as_uint(bv[gate].z), __float_as_uint(bv[gate].w));
        }
        stage = (stage + 1) % NSTAGE;
    }

    // ---- fused epilogue ----
    const int colg = h0 + wn * 8 + tg * 2;
    const float2 bF2 = *reinterpret_cast<const float2*>(bfp + colg);
    const float2 bI2 = *reinterpret_cast<const float2*>(bip + colg);
    const float2 bC2 = *reinterpret_cast<const float2*>(bcp + colg);
    const float2 bO2 = *reinterpret_cast<const float2*>(bop + colg);
    const size_t BH = (size_t)Bsz * Hsz;

    #pragma unroll
    for (int i = 0; i < 4; ++i) {
        #pragma unroll
        for (int half = 0; half < 2; ++half) {
            const int row = m0 + rb + i * 16 + g + half * 8;
            const int t0 = half * 2;
            const float2 ct2 =
                *reinterpret_cast<const float2*>(c_t + (size_t)row * Hsz + colg);
            float hv[2], cv[2];
            #pragma unroll
            for (int u = 0; u < 2; ++u) {
                const float fpre = acc[i][0][t0 + u] + ((u == 0) ? bF2.x : bF2.y);
                const float ipre = acc[i][1][t0 + u] + ((u == 0) ? bI2.x : bI2.y);
                const float cpre = acc[i][2][t0 + u] + ((u == 0) ? bC2.x : bC2.y);
                const float opre = acc[i][3][t0 + u] + ((u == 0) ? bO2.x : bO2.y);
                const float fv = sigf(fpre);
                const float iv = sigf(ipre);
                const float gv = tanhf(cpre);
                const float ov = sigf(opre);
                const float ctv = (u == 0) ? ct2.x : ct2.y;
                cv[u] = fv * ctv + iv * gv;
                hv[u] = ov * tanhf(cv[u]);
            }
            const size_t off = (size_t)row * Hsz + colg;
            const float2 h2 = make_float2(hv[0], hv[1]);
            const float2 c2 = make_float2(cv[0], cv[1]);
            for (int ch = 0; ch < nchunks - 1; ++ch)
                *reinterpret_cast<float2*>(out + (size_t)ch * BH + off) = h2;
            *reinterpret_cast<float2*>(out + (size_t)(nchunks - 1) * BH + off) =
                (nchunks > 1) ? c2 : h2;
        }
    }
}

// ---------------------------------------------------------------------------
extern "C" void kernel_launch(void* const* d_in, const int* in_sizes, int n_in,
                              void* d_out, int out_size)
{
    const float* x   = (const float*)d_in[0];
    const float* h_t = (const float*)d_in[1];
    const float* c_t = (const float*)d_in[2];
    const float* Wf  = (const float*)d_in[3];
    const float* bf  = (const float*)d_in[4];
    const float* Wi  = (const float*)d_in[5];
    const float* bi  = (const float*)d_in[6];
    const float* Wc  = (const float*)d_in[7];
    const float* bc  = (const float*)d_in[8];
    const float* Wo  = (const float*)d_in[9];
    const float* bo  = (const float*)d_in[10];

    cudaFuncSetAttribute(lstm_gemm_fused, cudaFuncAttributeMaxDynamicSharedMemorySize,
                         SMEM_BYTES);

    lstm_prepass_a<<<(unsigned)((A_ELEMS / 4 + 255) / 256), 256>>>(h_t, x);
    dim3 tg(Ksz / 32, Hsz / 32, 4);
    lstm_prepass_w<<<tg, dim3(32, 8)>>>(Wf, Wi, Wc, Wo);

    int nchunks = out_size / (Bsz * Hsz);
    if (nchunks < 1) nchunks = 1;
    dim3 grid(Hsz / 32, Bsz / BM);   // 32 x 64 = 2048 CTAs
    lstm_gemm_fused<<<grid, 256, SMEM_BYTES>>>(c_t, bf, bi, bc, bo,
                                               (float*)d_out, nchunks);
}

// round 15
// speedup vs baseline: 1.0489x; 1.0489x over previous
#include <cuda_runtime.h>
#include <cstdint>
#include <math.h>

// ===========================================================================
// LSTM cell, legacy tensor path (sm_100: no tcgen05).
//   Prepass A: tf32-round concat(h_t,x), k-PERMUTED per 32-block:
//     pos(k) = (k&3)*8 + ((k>>2)&7)  -> mma fragment elems contiguous.
//   Prepass W: tiled transpose to [gate][h][k-permuted], tf32-round.
//   GEMM: TF32 mma.sync m16n8k8, 3-stage cp.async pipeline, LDS.128 fragment
//   loads STREAMED per m-fragment (max 24 extra live regs -> no spills under
//   the 128-reg launch_bounds cap; R14 batched all fragments and spilled).
//   CTA tile: 128 rows x (4 gates x 32 H-cols); fused LSTM epilogue.
// ===========================================================================

namespace {
constexpr int Bsz = 8192, Hsz = 1024, Ksz = 2048;
constexpr int BM = 128, BK = 32;
constexpr int LDA = 36;              // 32 floats + 4 pad
constexpr int LDB = 36;
constexpr int A_STRIDE = BM * LDA;   // 4608 floats
constexpr int B_STRIDE = 128 * LDB;  // 4608 floats
constexpr int NSTAGE = 3;
constexpr int SMEM_FLOATS = NSTAGE * (A_STRIDE + B_STRIDE);   // 27648
constexpr int SMEM_BYTES = SMEM_FLOATS * 4;                   // 110592

constexpr size_t A_ELEMS = (size_t)Bsz * Ksz;   // 16M
constexpr size_t W_ELEMS = 4ull * Ksz * Hsz;    // 8M (Ksz*Hsz = 2^21)
}

__device__ float g_A[A_ELEMS];   // [m][k-permuted], tf32-rounded
__device__ float g_W[W_ELEMS];   // [gate][h][k-permuted], tf32-rounded

__device__ __forceinline__ void cp16(float* smem_dst, const float* gsrc) {
    uint32_t s = (uint32_t)__cvta_generic_to_shared(smem_dst);
    asm volatile("cp.async.cg.shared.global [%0], [%1], 16;" :: "r"(s), "l"(gsrc));
}
__device__ __forceinline__ uint32_t f2tf(float f) {
    uint32_t r; asm("cvt.rna.tf32.f32 %0, %1;" : "=r"(r) : "f"(f)); return r;
}
__device__ __forceinline__ float tf32r(float f) { return __uint_as_float(f2tf(f)); }
__device__ __forceinline__ void mma_tf32(float* c, uint32_t a0, uint32_t a1,
                                         uint32_t a2, uint32_t a3,
                                         uint32_t b0, uint32_t b1) {
    asm volatile(
        "mma.sync.aligned.m16n8k8.row.col.f32.tf32.tf32.f32 "
        "{%0,%1,%2,%3}, {%4,%5,%6,%7}, {%8,%9}, {%0,%1,%2,%3};"
        : "+f"(c[0]), "+f"(c[1]), "+f"(c[2]), "+f"(c[3])
        : "r"(a0), "r"(a1), "r"(a2), "r"(a3), "r"(b0), "r"(b1));
}
__device__ __forceinline__ float sigf(float v) { return 1.f / (1.f + __expf(-v)); }
__device__ __forceinline__ int kperm(int k) { return ((k & 3) << 3) | ((k >> 2) & 7); }

// ---------------------------------------------------------------------------
__global__ __launch_bounds__(256)
void lstm_prepass_a(const float* __restrict__ h_t, const float* __restrict__ x)
{
    const size_t i4 = (size_t)blockIdx.x * 256 + threadIdx.x;
    if (i4 >= A_ELEMS / 4) return;
    const size_t e = i4 * 4;
    const int m = (int)(e >> 11), k = (int)(e & 2047);
    const float* src = (k < 1024) ? (h_t + (size_t)m * 1024 + k)
                                  : (x + (size_t)m * 1024 + (k - 1024));
    const float4 v = *reinterpret_cast<const float4*>(src);
    float* dstb = g_A + (size_t)m * Ksz + (k & ~31);
    dstb[kperm(k + 0)] = tf32r(v.x);
    dstb[kperm(k + 1)] = tf32r(v.y);
    dstb[kperm(k + 2)] = tf32r(v.z);
    dstb[kperm(k + 3)] = tf32r(v.w);
}

__global__ __launch_bounds__(256)
void lstm_prepass_w(const float* __restrict__ Wf, const float* __restrict__ Wi,
                    const float* __restrict__ Wc, const float* __restrict__ Wo)
{
    __shared__ float t[32][33];
    const int gate = blockIdx.z;
    const float* W = (gate == 0) ? Wf : (gate == 1) ? Wi : (gate == 2) ? Wc : Wo;
    const int k0 = blockIdx.x * 32, h0 = blockIdx.y * 32;
    const int tx = threadIdx.x, ty = threadIdx.y;   // 32 x 8
    #pragma unroll
    for (int i = 0; i < 4; ++i)
        t[ty + i * 8][tx] = tf32r(W[(size_t)(k0 + ty + i * 8) * Hsz + h0 + tx]);
    __syncthreads();
    float* dst = g_W + (size_t)gate * (Ksz * Hsz);
    const int kp = k0 + kperm(tx);
    #pragma unroll
    for (int i = 0; i < 4; ++i)
        dst[(size_t)(h0 + ty + i * 8) * Ksz + kp] = t[tx][ty + i * 8];
}

// ---------------------------------------------------------------------------
__device__ __forceinline__ void prefetch_tiles(float* smem, int stage, int k0,
                                               int m0, int h0, int tid)
{
    float* As  = smem + stage * A_STRIDE;
    float* Bsm = smem + NSTAGE * A_STRIDE + stage * B_STRIDE;
    #pragma unroll
    for (int it = 0; it < 4; ++it) {            // A: 128 m-rows x 32 floats
        const int lin = tid + it * 256;
        const int r = lin >> 3, q = lin & 7;
        cp16(&As[r * LDA + q * 4], g_A + (size_t)(m0 + r) * Ksz + k0 + q * 4);
    }
    #pragma unroll
    for (int it = 0; it < 4; ++it) {            // B: 128 n-rows (4 gates x 32 h)
        const int lin = tid + it * 256;
        const int r = lin >> 3, q = lin & 7;
        const int gate = r >> 5, hc = r & 31;
        cp16(&Bsm[r * LDB + q * 4],
             g_W + (size_t)gate * (Ksz * Hsz) + (size_t)(h0 + hc) * Ksz + k0 + q * 4);
    }
    asm volatile("cp.async.commit_group;");
}

__global__ __launch_bounds__(256, 2)
void lstm_gemm_fused(const float* __restrict__ c_t,
                     const float* __restrict__ bfp, const float* __restrict__ bip,
                     const float* __restrict__ bcp, const float* __restrict__ bop,
                     float* __restrict__ out, int nchunks)
{
    extern __shared__ float smem[];
    const int tid = threadIdx.x;
    const int m0 = blockIdx.y * BM;
    const int h0 = blockIdx.x * 32;

    const int warp = tid >> 5, lane = tid & 31;
    const int wm = warp >> 2, wn = warp & 3;   // 2 x 4 warps
    const int rb = wm * 64;
    const int g = lane >> 2, tg = lane & 3;

    float acc[4][4][4];                        // [m-frag][gate][reg]
    #pragma unroll
    for (int i = 0; i < 4; ++i)
        #pragma unroll
        for (int j = 0; j < 4; ++j)
            #pragma unroll
            for (int t = 0; t < 4; ++t) acc[i][j][t] = 0.f;

    const int KT = Ksz / BK;   // 64
    prefetch_tiles(smem, 0, 0, m0, h0, tid);
    prefetch_tiles(smem, 1, BK, m0, h0, tid);

    int stage = 0;
    for (int kt = 0; kt < KT; ++kt) {
        if (kt + 1 < KT) asm volatile("cp.async.wait_group 1;");
        else             asm volatile("cp.async.wait_group 0;");
        __syncthreads();
        if (kt + 2 < KT)
            prefetch_tiles(smem, (stage + 2) % NSTAGE, (kt + 2) * BK, m0, h0, tid);

        const float* As  = smem + stage * A_STRIDE;
        const float* Bsm = smem + NSTAGE * A_STRIDE + stage * B_STRIDE;

        // permuted row: float4 at tg*8 + h2*4 -> (x,y)=k-step h2*16, (z,w)=h2*16+8
        #pragma unroll
        for (int h2 = 0; h2 < 2; ++h2) {
            const int fo = tg * 8 + h2 * 4;
            float4 bv[4];
            #pragma unroll
            for (int gate = 0; gate < 4; ++gate) {
                const int c0 = gate * 32 + wn * 8 + g;
                bv[gate] = *reinterpret_cast<const float4*>(&Bsm[c0 * LDB + fo]);
            }
            #pragma unroll
            for (int i = 0; i < 4; ++i) {       // stream A fragments: 8 regs live
                const int r0 = rb + i * 16 + g;
                const float4 a0 = *reinterpret_cast<const float4*>(&As[r0 * LDA + fo]);
                const float4 a1 = *reinterpret_cast<const float4*>(&As[(r0 + 8) * LDA + fo]);
                #pragma unroll
                for (int gate = 0; gate < 4; ++gate)
                    mma_tf32(acc[i][gate],
                             __float_as_uint(a0.x), __float_as_uint(a1.x),
                             __float_as_uint(a0.y), __float_as_uint(a1.y),
                             __float_as_uint(bv[gate].x), __float_as_uint(bv[gate].y));
                #pragma unroll
                for (int gate = 0; gate < 4; ++gate)
                    mma_tf32(acc[i][gate],
                             __float_as_uint(a0.z), __float_as_uint(a1.z),
                             __float_as_uint(a0.w), __float_as_uint(a1.w),
                             __float_as_uint(bv[gate].z), __float_as_uint(bv[gate].w));
            }
        }
        stage = (stage + 1) % NSTAGE;
    }

    // ---- fused epilogue ----
    const int colg = h0 + wn * 8 + tg * 2;
    const float2 bF2 = *reinterpret_cast<const float2*>(bfp + colg);
    const float2 bI2 = *reinterpret_cast<const float2*>(bip + colg);
    const float2 bC2 = *reinterpret_cast<const float2*>(bcp + colg);
    const float2 bO2 = *reinterpret_cast<const float2*>(bop + colg);
    const size_t BH = (size_t)Bsz * Hsz;

    #pragma unroll
    for (int i = 0; i < 4; ++i) {
        #pragma unroll
        for (int half = 0; half < 2; ++half) {
            const int row = m0 + rb + i * 16 + g + half * 8;
            const int t0 = half * 2;
            const float2 ct2 =
                *reinterpret_cast<const float2*>(c_t + (size_t)row * Hsz + colg);
            float hv[2], cv[2];
            #pragma unroll
            for (int u = 0; u < 2; ++u) {
                const float fpre = acc[i][0][t0 + u] + ((u == 0) ? bF2.x : bF2.y);
                const float ipre = acc[i][1][t0 + u] + ((u == 0) ? bI2.x : bI2.y);
                const float cpre = acc[i][2][t0 + u] + ((u == 0) ? bC2.x : bC2.y);
                const float opre = acc[i][3][t0 + u] + ((u == 0) ? bO2.x : bO2.y);
                const float fv = sigf(fpre);
                const float iv = sigf(ipre);
                const float gv = tanhf(cpre);
                const float ov = sigf(opre);
                const float ctv = (u == 0) ? ct2.x : ct2.y;
                cv[u] = fv * ctv + iv * gv;
                hv[u] = ov * tanhf(cv[u]);
            }
            const size_t off = (size_t)row * Hsz + colg;
            const float2 h2v = make_float2(hv[0], hv[1]);
            const float2 c2v = make_float2(cv[0], cv[1]);
            for (int ch = 0; ch < nchunks - 1; ++ch)
                *reinterpret_cast<float2*>(out + (size_t)ch * BH + off) = h2v;
            *reinterpret_cast<float2*>(out + (size_t)(nchunks - 1) * BH + off) =
                (nchunks > 1) ? c2v : h2v;
        }
    }
}

// ---------------------------------------------------------------------------
extern "C" void kernel_launch(void* const* d_in, const int* in_sizes, int n_in,
                              void* d_out, int out_size)
{
    const float* x   = (const float*)d_in[0];
    const float* h_t = (const float*)d_in[1];
    const float* c_t = (const float*)d_in[2];
    const float* Wf  = (const float*)d_in[3];
    const float* bf  = (const float*)d_in[4];
    const float* Wi  = (const float*)d_in[5];
    const float* bi  = (const float*)d_in[6];
    const float* Wc  = (const float*)d_in[7];
    const float* bc  = (const float*)d_in[8];
    const float* Wo  = (const float*)d_in[9];
    const float* bo  = (const float*)d_in[10];

    cudaFuncSetAttribute(lstm_gemm_fused, cudaFuncAttributeMaxDynamicSharedMemorySize,
                         SMEM_BYTES);

    lstm_prepass_a<<<(unsigned)((A_ELEMS / 4 + 255) / 256), 256>>>(h_t, x);
    dim3 tg(Ksz / 32, Hsz / 32, 4);
    lstm_prepass_w<<<tg, dim3(32, 8)>>>(Wf, Wi, Wc, Wo);

    int nchunks = out_size / (Bsz * Hsz);
    if (nchunks < 1) nchunks = 1;
    dim3 grid(Hsz / 32, Bsz / BM);   // 32 x 64 = 2048 CTAs
    lstm_gemm_fused<<<grid, 256, SMEM_BYTES>>>(c_t, bf, bi, bc, bo,
                                               (float*)d_out, nchunks);
}